// round 13
// baseline (speedup 1.0000x reference)
#include <cuda_runtime.h>
#include <cuda_fp16.h>
#include <cstdint>

#define BATCH 4
#define SEQ   4096
#define DIM   768
#define NTOK  (BATCH*SEQ)

// ---------------- scratch (__device__ globals: allocation-free rule) --------
__device__ __half g_Xhi [(size_t)NTOK * DIM];
__device__ __half g_Xlo [(size_t)NTOK * DIM];
__device__ __half g_WThi[3ull * DIM * DIM];               // B side: hi only
__device__ __half g_Qhi [(size_t)NTOK * DIM];
__device__ __half g_Qlo [(size_t)NTOK * DIM];
__device__ __half g_Khi [(size_t)NTOK * DIM];             // fp16 only (B side)
__device__ __half g_VThi[(size_t)BATCH * DIM * SEQ];      // V^T, written by proj epilogue
__device__ __half g_Phi [(size_t)BATCH * SEQ * SEQ];      // exp(scores)/64, fp16
__device__ float g_partial[(size_t)NTOK * 32];            // per-(row,tile) sums
__device__ float g_rowsum [(size_t)NTOK];                 // final row sums

// ---------------- PTX helpers (arch-agnostic, sm_80-class) ------------------
__device__ __forceinline__ uint32_t smem_u32(const void* p) {
    uint32_t a;
    asm("{ .reg .u64 t; cvta.to.shared.u64 t, %1; cvt.u32.u64 %0, t; }"
        : "=r"(a) : "l"(p));
    return a;
}
__device__ __forceinline__ void cp16(uint32_t dst, const void* src) {
    asm volatile("cp.async.cg.shared.global [%0], [%1], 16;"
                 :: "r"(dst), "l"(src) : "memory");
}
#define CP_COMMIT() asm volatile("cp.async.commit_group;" ::: "memory")
#define CP_WAIT(N)  asm volatile("cp.async.wait_group %0;" :: "n"(N) : "memory")

__device__ __forceinline__ void ldsm_x4(uint32_t* r, uint32_t addr) {
    asm volatile("ldmatrix.sync.aligned.m8n8.x4.shared.b16 {%0,%1,%2,%3}, [%4];"
                 : "=r"(r[0]), "=r"(r[1]), "=r"(r[2]), "=r"(r[3]) : "r"(addr));
}
__device__ __forceinline__ void mma16816(float* d, const uint32_t* a, const uint32_t* b) {
    asm volatile(
        "mma.sync.aligned.m16n8k16.row.col.f32.f16.f16.f32 "
        "{%0,%1,%2,%3}, {%4,%5,%6,%7}, {%8,%9}, {%0,%1,%2,%3};"
        : "+f"(d[0]), "+f"(d[1]), "+f"(d[2]), "+f"(d[3])
        : "r"(a[0]), "r"(a[1]), "r"(a[2]), "r"(a[3]), "r"(b[0]), "r"(b[1]));
}

__device__ __forceinline__ void split2h(float a, float b, uint32_t& h, uint32_t& l) {
    __half2 hv = __floats2half2_rn(a, b);
    float2 f = __half22float2(hv);
    __half2 lv = __floats2half2_rn(a - f.x, b - f.y);
    h = *reinterpret_cast<uint32_t*>(&hv);
    l = *reinterpret_cast<uint32_t*>(&lv);
}
__device__ __forceinline__ uint32_t pack2h(float a, float b) {
    __half2 hv = __floats2half2_rn(a, b);
    return *reinterpret_cast<uint32_t*>(&hv);
}
__device__ __forceinline__ __half h_hi(float v) { return __float2half_rn(v); }

#define LDSE 72                        // smem row stride (fp16), conflict-free ldsm
#define SM_SCALE 0.03608439182435161f  // 1/sqrt(768)
#define P_SCALE  0.015625f             // store exp/64

// ============================================================================
// CORE A (2-term, 32x64 warp tile, 128x128 CTA, 2 CTAs/SM) — proj_q, scores
// ============================================================================
#define BUFB (128 * LDSE * 2)          // 18432 B
#define SMEM_A_BYTES 110592            // 2 stages x 3 buffers

// MODE 1: split fp16 Chi/Clo (proj Q).
// MODE 2: exp/64 + causal mask + row partial sums -> g_partial; fp16 out.
template <int MODE>
__device__ __forceinline__ void gemm_2t(
    const __half* __restrict__ Ahi, const __half* __restrict__ Alo, int lda,
    const __half* __restrict__ Bhi, int ldb,
    __half* __restrict__ Chi, __half* __restrict__ Clo,
    int ldc, int i0, int j0, int K, int rs_off)
{
    extern __shared__ __align__(16) uint16_t dsm[];
    const uint32_t sb = smem_u32(dsm);

    const int tid  = threadIdx.x;
    const int wid  = tid >> 5;
    const int lane = tid & 31;
    const int m0 = (wid & 3) * 32;
    const int n0 = (wid >> 2) * 64;

    const int a_row = lane & 15;
    const int a_col = (lane >> 4) * 8;
    const int b_row = ((lane >> 4) & 1) * 8 + (lane & 7);
    const int b_col = ((lane >> 3) & 1) * 8;

    const __half* gsrc[3] = {Ahi, Alo, Bhi};
    const int glda[3] = {lda, lda, ldb};
    const int grow[3] = {i0, i0, j0};

    const int nk = K >> 6;

    auto stage = [&](int s, int kt) {
#pragma unroll
        for (int b = 0; b < 3; ++b) {
            uint32_t base = sb + (uint32_t)((s * 3 + b) * BUFB);
            const __half* g = gsrc[b];
#pragma unroll
            for (int k = 0; k < 4; ++k) {
                int u = tid + k * 256;
                int r = u >> 3, c = (u & 7) * 8;
                cp16(base + (uint32_t)(r * LDSE + c) * 2,
                     g + (size_t)(grow[b] + r) * glda[b] + kt + c);
            }
        }
        CP_COMMIT();
    };

    float acc[2][8][4] = {};

    stage(0, 0);
    for (int it = 0; it < nk; ++it) {
        const int s = it & 1;
        if (it + 1 < nk) { stage(s ^ 1, (it + 1) << 6); CP_WAIT(1); }
        else             { CP_WAIT(0); }
        __syncthreads();

        const uint32_t bAhi = sb + (uint32_t)((s * 3 + 0) * BUFB);
        const uint32_t bAlo = sb + (uint32_t)((s * 3 + 1) * BUFB);
        const uint32_t bBhi = sb + (uint32_t)((s * 3 + 2) * BUFB);

#pragma unroll
        for (int kk = 0; kk < 64; kk += 16) {
            uint32_t aH[2][4], aL[2][4];
#pragma unroll
            for (int mi = 0; mi < 2; ++mi) {
                uint32_t off = (uint32_t)((m0 + mi * 16 + a_row) * LDSE + kk + a_col) * 2;
                ldsm_x4(aH[mi], bAhi + off);
                ldsm_x4(aL[mi], bAlo + off);
            }
#pragma unroll
            for (int nj = 0; nj < 4; ++nj) {
                uint32_t off = (uint32_t)((n0 + nj * 16 + b_row) * LDSE + kk + b_col) * 2;
                uint32_t bh[4];
                ldsm_x4(bh, bBhi + off);
#pragma unroll
                for (int mi = 0; mi < 2; ++mi) {
                    float* a0 = acc[mi][nj * 2];
                    float* a1 = acc[mi][nj * 2 + 1];
                    mma16816(a0, aH[mi], bh);
                    mma16816(a1, aH[mi], bh + 2);
                    mma16816(a0, aL[mi], bh);
                    mma16816(a1, aL[mi], bh + 2);
                }
            }
        }
        __syncthreads();
    }

    const int tr = lane >> 2;
    const int tc = (lane & 3) * 2;

    if (MODE == 1) {
#pragma unroll
        for (int mi = 0; mi < 2; ++mi)
#pragma unroll
            for (int nj = 0; nj < 8; ++nj) {
                int row = i0 + m0 + mi * 16 + tr;
                int col = j0 + n0 + nj * 8 + tc;
                uint32_t h, l;
                size_t idx = (size_t)row * ldc + col;
                split2h(acc[mi][nj][0], acc[mi][nj][1], h, l);
                *reinterpret_cast<uint32_t*>(Chi + idx) = h;
                *reinterpret_cast<uint32_t*>(Clo + idx) = l;
                idx = (size_t)(row + 8) * ldc + col;
                split2h(acc[mi][nj][2], acc[mi][nj][3], h, l);
                *reinterpret_cast<uint32_t*>(Chi + idx) = h;
                *reinterpret_cast<uint32_t*>(Clo + idx) = l;
            }
    } else {  // MODE 2
        float* red = reinterpret_cast<float*>(dsm);
        const int nwid = wid >> 2;
#pragma unroll
        for (int mi = 0; mi < 2; ++mi) {
#pragma unroll
            for (int rp = 0; rp < 2; ++rp) {
                const int lrow = m0 + mi * 16 + tr + rp * 8;
                const int row  = i0 + lrow;
                float part = 0.f;
#pragma unroll
                for (int nj = 0; nj < 8; ++nj) {
                    int col = j0 + n0 + nj * 8 + tc;
                    float e0 = (col     <= row)
                        ? __expf(acc[mi][nj][rp * 2]     * SM_SCALE) * P_SCALE : 0.f;
                    float e1 = (col + 1 <= row)
                        ? __expf(acc[mi][nj][rp * 2 + 1] * SM_SCALE) * P_SCALE : 0.f;
                    size_t idx = (size_t)row * ldc + col;
                    *reinterpret_cast<uint32_t*>(Chi + idx) = pack2h(e0, e1);
                    part += e0 + e1;
                }
                part += __shfl_xor_sync(0xffffffffu, part, 1);
                part += __shfl_xor_sync(0xffffffffu, part, 2);
                if ((lane & 3) == 0) red[lrow * 2 + nwid] = part;
            }
        }
        __syncthreads();
        if (tid < 128) {
            float s = red[tid * 2] + red[tid * 2 + 1];
            g_partial[(size_t)(rs_off + i0 + tid) * 32 + (j0 >> 7)] = s;
        }
    }
}

// ============================================================================
// CORE B (1-term, 64x64 warp tile, 128x256 CTA, 1 CTA/SM, 3-stage) —
//   proj_k, proj_v(->VT), pv
// ============================================================================
#define ABUF (128 * LDSE * 2)          // 18432 B
#define BBUF (256 * LDSE * 2)          // 36864 B
#define STGB (ABUF + BBUF)             // 55296 B
#define SMEM_B_BYTES (3 * STGB)        // 165888 B

// MODE 4: fp16 Chi (proj K).  MODE 5: V -> g_VThi transposed via smem.
// MODE 3: fp32 out scaled by 1/g_rowsum (pv).
template <int MODE>
__device__ __forceinline__ void gemm_1t_big(
    const __half* __restrict__ Ahi, int lda,
    const __half* __restrict__ Bhi, int ldb,
    float* __restrict__ C, __half* __restrict__ Chi,
    int ldc, int i0, int j0, int K, int rs_off)
{
    extern __shared__ __align__(16) uint16_t dsm[];
    const uint32_t sb = smem_u32(dsm);

    const int tid  = threadIdx.x;
    const int wid  = tid >> 5;
    const int lane = tid & 31;
    const int m0 = (wid & 1) * 64;       // 2 m-warps x 64
    const int n0 = (wid >> 1) * 64;      // 4 n-warps x 64

    const int a_row = lane & 15;
    const int a_col = (lane >> 4) * 8;
    const int b_row = ((lane >> 4) & 1) * 8 + (lane & 7);
    const int b_col = ((lane >> 3) & 1) * 8;

    const int nk = K >> 6;

    auto stage = [&](int s, int kt) {
        uint32_t base = sb + (uint32_t)(s * STGB);
#pragma unroll
        for (int k = 0; k < 4; ++k) {                // A: 1024 chunks
            int u = tid + k * 256;
            int r = u >> 3, c = (u & 7) * 8;
            cp16(base + (uint32_t)(r * LDSE + c) * 2,
                 Ahi + (size_t)(i0 + r) * lda + kt + c);
        }
#pragma unroll
        for (int k = 0; k < 8; ++k) {                // B: 2048 chunks
            int u = tid + k * 256;
            int r = u >> 3, c = (u & 7) * 8;
            cp16(base + ABUF + (uint32_t)(r * LDSE + c) * 2,
                 Bhi + (size_t)(j0 + r) * ldb + kt + c);
        }
        CP_COMMIT();
    };

    float acc[4][8][4] = {};

    stage(0, 0);
    if (nk > 1) stage(1, 64);
    for (int it = 0; it < nk; ++it) {
        const int s = it % 3;
        if (it + 2 < nk)      { stage((it + 2) % 3, (it + 2) << 6); CP_WAIT(2); }
        else if (it + 2 == nk) { CP_WAIT(1); }
        else                   { CP_WAIT(0); }
        __syncthreads();

        const uint32_t bA = sb + (uint32_t)(s * STGB);
        const uint32_t bB = bA + ABUF;

#pragma unroll
        for (int kk = 0; kk < 64; kk += 16) {
            uint32_t aH[4][4];
#pragma unroll
            for (int mi = 0; mi < 4; ++mi) {
                uint32_t off = (uint32_t)((m0 + mi * 16 + a_row) * LDSE + kk + a_col) * 2;
                ldsm_x4(aH[mi], bA + off);
            }
#pragma unroll
            for (int nj = 0; nj < 4; ++nj) {
                uint32_t off = (uint32_t)((n0 + nj * 16 + b_row) * LDSE + kk + b_col) * 2;
                uint32_t bh[4];
                ldsm_x4(bh, bB + off);
#pragma unroll
                for (int mi = 0; mi < 4; ++mi) {
                    mma16816(acc[mi][nj * 2],     aH[mi], bh);
                    mma16816(acc[mi][nj * 2 + 1], aH[mi], bh + 2);
                }
            }
        }
        __syncthreads();
    }

    const int tr = lane >> 2;
    const int tc = (lane & 3) * 2;

    if (MODE == 4) {
#pragma unroll
        for (int mi = 0; mi < 4; ++mi)
#pragma unroll
            for (int nj = 0; nj < 8; ++nj) {
                int row = i0 + m0 + mi * 16 + tr;
                int col = j0 + n0 + nj * 8 + tc;
                *reinterpret_cast<uint32_t*>(Chi + (size_t)row * ldc + col) =
                    pack2h(acc[mi][nj][0], acc[mi][nj][1]);
                *reinterpret_cast<uint32_t*>(Chi + (size_t)(row + 8) * ldc + col) =
                    pack2h(acc[mi][nj][2], acc[mi][nj][3]);
            }
    } else if (MODE == 5) {
        // V tile [128 tok x 256 d] -> smem [d][tok] -> coalesced g_VThi writes
        uint16_t* vt = dsm;                           // [256][136] fp16
#pragma unroll
        for (int mi = 0; mi < 4; ++mi)
#pragma unroll
            for (int nj = 0; nj < 8; ++nj) {
                int r = m0 + mi * 16 + tr;
                int c = n0 + nj * 8 + tc;
                vt[(c    ) * 136 + r    ] = __half_as_ushort(h_hi(acc[mi][nj][0]));
                vt[(c + 1) * 136 + r    ] = __half_as_ushort(h_hi(acc[mi][nj][1]));
                vt[(c    ) * 136 + r + 8] = __half_as_ushort(h_hi(acc[mi][nj][2]));
                vt[(c + 1) * 136 + r + 8] = __half_as_ushort(h_hi(acc[mi][nj][3]));
            }
        __syncthreads();
        const int b = i0 >> 12;                       // batch (tile within one batch)
        const int seqr = i0 & (SEQ - 1);
#pragma unroll
        for (int k = 0; k < 16; ++k) {                // 4096 8-tok chunks
            int u = tid + k * 256;
            int d = u >> 4, tk = (u & 15) * 8;
            uint4 v = *reinterpret_cast<uint4*>(&vt[d * 136 + tk]);
            *reinterpret_cast<uint4*>(
                g_VThi + ((size_t)b * DIM + j0 + d) * SEQ + seqr + tk) = v;
        }
    } else {  // MODE 3: pv, normalize by row sums
#pragma unroll
        for (int mi = 0; mi < 4; ++mi) {
            int row = i0 + m0 + mi * 16 + tr;
            float s0 = 1.0f / g_rowsum[rs_off + row];
            float s1 = 1.0f / g_rowsum[rs_off + row + 8];
#pragma unroll
            for (int nj = 0; nj < 8; ++nj) {
                int col = j0 + n0 + nj * 8 + tc;
                *reinterpret_cast<float2*>(C + (size_t)row * ldc + col) =
                    make_float2(acc[mi][nj][0] * s0, acc[mi][nj][1] * s0);
                *reinterpret_cast<float2*>(C + (size_t)(row + 8) * ldc + col) =
                    make_float2(acc[mi][nj][2] * s1, acc[mi][nj][3] * s1);
            }
        }
    }
}

// ---------------- GEMM stage kernels ------------------------------------------
__global__ void __launch_bounds__(256, 2)
proj_q_tc()
{
    gemm_2t<1>(g_Xhi, g_Xlo, DIM, g_WThi, DIM,
               g_Qhi, g_Qlo, DIM, blockIdx.y * 128, blockIdx.x * 128, DIM, 0);
}

__global__ void __launch_bounds__(256, 1)
proj_k_tc()
{
    gemm_1t_big<4>(g_Xhi, DIM, g_WThi + (size_t)DIM * DIM, DIM,
                   nullptr, g_Khi, DIM,
                   blockIdx.y * 128, blockIdx.x * 256, DIM, 0);
}

__global__ void __launch_bounds__(256, 1)
proj_v_tc()
{
    gemm_1t_big<5>(g_Xhi, DIM, g_WThi + 2ull * DIM * DIM, DIM,
                   nullptr, nullptr, DIM,
                   blockIdx.y * 128, blockIdx.x * 256, DIM, 0);
}

__global__ void __launch_bounds__(256, 2)
scores_tc()
{
    // triangular tile decode: t -> (i >= j)
    const int t = blockIdx.x;
    int i = (int)((sqrtf(8.0f * t + 1.0f) - 1.0f) * 0.5f);
    while ((i + 1) * (i + 2) / 2 <= t) ++i;
    while (i * (i + 1) / 2 > t) --i;
    const int j = t - i * (i + 1) / 2;
    const int i0 = i * 128, j0 = j * 128;

    const size_t off = (size_t)blockIdx.z * SEQ * DIM;
    __half* Ch = g_Phi + (size_t)blockIdx.z * SEQ * SEQ;
    gemm_2t<2>(g_Qhi + off, g_Qlo + off, DIM, g_Khi + off, DIM,
               Ch, nullptr, SEQ, i0, j0, DIM, blockIdx.z * SEQ);
}

__global__ void __launch_bounds__(256, 1)
pv_tc(float* __restrict__ out)
{
    const int i0 = blockIdx.y * 128, j0 = blockIdx.x * 256;
    const size_t poff = (size_t)blockIdx.z * SEQ * SEQ;
    const size_t voff = (size_t)blockIdx.z * DIM * SEQ;
    float* C = out + (size_t)blockIdx.z * SEQ * DIM;
    gemm_1t_big<3>(g_Phi + poff, SEQ, g_VThi + voff, SEQ,
                   C, nullptr, DIM, i0, j0, i0 + 128, blockIdx.z * SEQ);
}

// ---------------- rowsum reduce (deterministic) ---------------------------------
__global__ void __launch_bounds__(256)
reduce_rowsum()
{
    const int i = blockIdx.x * 256 + threadIdx.x;
    const int q = i & (SEQ - 1);
    const int nt = (q >> 7) + 1;
    const float* p = g_partial + (size_t)i * 32;
    float s = 0.f;
    for (int t = 0; t < nt; ++t) s += p[t];
    g_rowsum[i] = s;
}

// ---------------- conversion / transpose kernels -------------------------------
__global__ void conv_x(const float* __restrict__ X)
{
    size_t i = (size_t)blockIdx.x * blockDim.x + threadIdx.x;
    const size_t n4 = (size_t)NTOK * DIM / 4;
    for (; i < n4; i += (size_t)gridDim.x * blockDim.x) {
        float4 v = reinterpret_cast<const float4*>(X)[i];
        uint32_t h0, l0, h1, l1;
        split2h(v.x, v.y, h0, l0);
        split2h(v.z, v.w, h1, l1);
        reinterpret_cast<uint2*>(g_Xhi)[i] = make_uint2(h0, h1);
        reinterpret_cast<uint2*>(g_Xlo)[i] = make_uint2(l0, l1);
    }
}

__global__ void transpose_w(const float* __restrict__ Wq,
                            const float* __restrict__ Wk,
                            const float* __restrict__ Wv)
{
    const float* src = (blockIdx.z == 0) ? Wq : (blockIdx.z == 1) ? Wk : Wv;
    __half* dh = g_WThi + (size_t)blockIdx.z * DIM * DIM;
    __shared__ float t[32][33];
    const int bx = blockIdx.x * 32, by = blockIdx.y * 32;
    const int tx = threadIdx.x, ty = threadIdx.y;
#pragma unroll
    for (int j = 0; j < 32; j += 8)
        t[ty + j][tx] = src[(size_t)(by + ty + j) * DIM + bx + tx];
    __syncthreads();
#pragma unroll
    for (int j = 0; j < 32; j += 8)
        dh[(size_t)(bx + ty + j) * DIM + by + tx] = h_hi(t[tx][ty + j]);
}

// ---------------- launch ---------------------------------------------------------
extern "C" void kernel_launch(void* const* d_in, const int* in_sizes, int n_in,
                              void* d_out, int out_size)
{
    const float* x  = (const float*)d_in[0];
    const float* Wq = (const float*)d_in[1];
    const float* Wk = (const float*)d_in[2];
    const float* Wv = (const float*)d_in[3];
    float* out = (float*)d_out;

    cudaFuncSetAttribute(proj_q_tc, cudaFuncAttributeMaxDynamicSharedMemorySize, SMEM_A_BYTES);
    cudaFuncSetAttribute(scores_tc, cudaFuncAttributeMaxDynamicSharedMemorySize, SMEM_A_BYTES);
    cudaFuncSetAttribute(proj_k_tc, cudaFuncAttributeMaxDynamicSharedMemorySize, SMEM_B_BYTES);
    cudaFuncSetAttribute(proj_v_tc, cudaFuncAttributeMaxDynamicSharedMemorySize, SMEM_B_BYTES);
    cudaFuncSetAttribute(pv_tc,     cudaFuncAttributeMaxDynamicSharedMemorySize, SMEM_B_BYTES);

    dim3 t32(32, 8);
    conv_x<<<512, 256>>>(x);
    transpose_w<<<dim3(DIM / 32, DIM / 32, 3), t32>>>(Wq, Wk, Wv);
    proj_q_tc<<<dim3(DIM / 128, NTOK / 128), 256, SMEM_A_BYTES>>>();
    proj_k_tc<<<dim3(DIM / 256, NTOK / 128), 256, SMEM_B_BYTES>>>();
    proj_v_tc<<<dim3(DIM / 256, NTOK / 128), 256, SMEM_B_BYTES>>>();
    scores_tc<<<dim3(528, 1, BATCH), 256, SMEM_A_BYTES>>>();
    reduce_rowsum<<<NTOK / 256, 256>>>();
    pv_tc<<<dim3(DIM / 256, SEQ / 128, BATCH), 256, SMEM_B_BYTES>>>(out);
}

// round 14
// speedup vs baseline: 1.0495x; 1.0495x over previous
#include <cuda_runtime.h>
#include <cuda_fp16.h>
#include <cstdint>

#define BATCH 4
#define SEQ   4096
#define DIM   768
#define NTOK  (BATCH*SEQ)

// ---------------- scratch (__device__ globals: allocation-free rule) --------
__device__ __half g_Xhi [(size_t)NTOK * DIM];
__device__ __half g_Xlo [(size_t)NTOK * DIM];
__device__ __half g_WThi[3ull * DIM * DIM];               // B side: hi only
__device__ __half g_Qhi [(size_t)NTOK * DIM];
__device__ __half g_Qlo [(size_t)NTOK * DIM];
__device__ __half g_Khi [(size_t)NTOK * DIM];             // fp16 only (B side)
__device__ __half g_VThi[(size_t)BATCH * DIM * SEQ];      // V^T (written by proj_v epi)
__device__ __half g_Phi [(size_t)BATCH * SEQ * SEQ];      // exp(scores)/64, fp16
__device__ float g_partial[(size_t)NTOK * 32];            // per-(row,tile) sums
__device__ float g_rowsum [(size_t)NTOK];                 // final row sums

// ---------------- PTX helpers (arch-agnostic, sm_80-class) ------------------
__device__ __forceinline__ uint32_t smem_u32(const void* p) {
    uint32_t a;
    asm("{ .reg .u64 t; cvta.to.shared.u64 t, %1; cvt.u32.u64 %0, t; }"
        : "=r"(a) : "l"(p));
    return a;
}
__device__ __forceinline__ void cp16(uint32_t dst, const void* src) {
    asm volatile("cp.async.cg.shared.global [%0], [%1], 16;"
                 :: "r"(dst), "l"(src) : "memory");
}
#define CP_COMMIT() asm volatile("cp.async.commit_group;" ::: "memory")
#define CP_WAIT(N)  asm volatile("cp.async.wait_group %0;" :: "n"(N) : "memory")

__device__ __forceinline__ void ldsm_x4(uint32_t* r, uint32_t addr) {
    asm volatile("ldmatrix.sync.aligned.m8n8.x4.shared.b16 {%0,%1,%2,%3}, [%4];"
                 : "=r"(r[0]), "=r"(r[1]), "=r"(r[2]), "=r"(r[3]) : "r"(addr));
}
__device__ __forceinline__ void mma16816(float* d, const uint32_t* a, const uint32_t* b) {
    asm volatile(
        "mma.sync.aligned.m16n8k16.row.col.f32.f16.f16.f32 "
        "{%0,%1,%2,%3}, {%4,%5,%6,%7}, {%8,%9}, {%0,%1,%2,%3};"
        : "+f"(d[0]), "+f"(d[1]), "+f"(d[2]), "+f"(d[3])
        : "r"(a[0]), "r"(a[1]), "r"(a[2]), "r"(a[3]), "r"(b[0]), "r"(b[1]));
}

__device__ __forceinline__ void split2h(float a, float b, uint32_t& h, uint32_t& l) {
    __half2 hv = __floats2half2_rn(a, b);
    float2 f = __half22float2(hv);
    __half2 lv = __floats2half2_rn(a - f.x, b - f.y);
    h = *reinterpret_cast<uint32_t*>(&hv);
    l = *reinterpret_cast<uint32_t*>(&lv);
}
__device__ __forceinline__ uint32_t pack2h(float a, float b) {
    __half2 hv = __floats2half2_rn(a, b);
    return *reinterpret_cast<uint32_t*>(&hv);
}
__device__ __forceinline__ __half h_hi(float v) { return __float2half_rn(v); }

// ---------------- pipelined GEMM core (R12 shape: proven optimum) -------------
// C[128,128] = (Ahi[+Alo])[128,K] * Bhi[128,K]^T, fp16 MMA x NTERMS, fp32 accum.
// 256 threads, 4(m) x 2(n) warps, warp tile 32x64, k-step 64, 2 CTAs/SM.
// 2-term: 2-stage x 3 bufs; 1-term: 3-stage x 2 bufs (both 110.6 KB).
#define LDSE 72
#define BUFB (128 * LDSE * 2)        // 18432 B
#define SMEM_BYTES 110592

#define SM_SCALE 0.03608439182435161f   // 1/sqrt(768)
#define P_SCALE  0.015625f              // store exp/64

// MODE 1: split fp16 Chi/Clo (proj Q).   MODE 4: fp16 Chi (proj K).
// MODE 5: V -> g_VThi transposed via smem (proj V).
// MODE 2: exp/64 + causal mask + row partial sums; fp16 out (scores).
// MODE 3: fp32 C scaled by 1/g_rowsum[row] (pv).
template <int MODE, int NTERMS>
__device__ __forceinline__ void gemm_pipe(
    const __half* __restrict__ Ahi, const __half* __restrict__ Alo, int lda,
    const __half* __restrict__ Bhi, int ldb,
    float* __restrict__ C, __half* __restrict__ Chi, __half* __restrict__ Clo,
    int ldc, int i0, int j0, int K, int rs_off)
{
    extern __shared__ __align__(16) uint16_t dsm[];
    const uint32_t sb = smem_u32(dsm);

    const int tid  = threadIdx.x;
    const int wid  = tid >> 5;
    const int lane = tid & 31;
    const int m0 = (wid & 3) * 32;
    const int n0 = (wid >> 2) * 64;

    const int a_row = lane & 15;
    const int a_col = (lane >> 4) * 8;
    const int b_row = ((lane >> 4) & 1) * 8 + (lane & 7);
    const int b_col = ((lane >> 3) & 1) * 8;

    constexpr int NBUF   = NTERMS + 1;
    constexpr int NSTAGE = (NTERMS == 2) ? 2 : 3;
    const __half* gsrc[3] = {Ahi, (NTERMS == 2) ? Alo : Bhi, Bhi};
    const int glda[3] = {lda, (NTERMS == 2) ? lda : ldb, ldb};
    const int grow[3] = {i0, (NTERMS == 2) ? i0 : j0, j0};

    const int nk = K >> 6;

    auto stage = [&](int s, int kt) {
#pragma unroll
        for (int b = 0; b < NBUF; ++b) {
            uint32_t base = sb + (uint32_t)((s * NBUF + b) * BUFB);
            const __half* g = gsrc[b];
#pragma unroll
            for (int k = 0; k < 4; ++k) {
                int u = tid + k * 256;
                int r = u >> 3, c = (u & 7) * 8;
                cp16(base + (uint32_t)(r * LDSE + c) * 2,
                     g + (size_t)(grow[b] + r) * glda[b] + kt + c);
            }
        }
        CP_COMMIT();
    };

    float acc[2][8][4] = {};

    stage(0, 0);
    if (NSTAGE == 3 && nk > 1) stage(1, 64);
    for (int it = 0; it < nk; ++it) {
        const int s = it % NSTAGE;
        if (it + NSTAGE - 1 < nk) {
            stage((it + NSTAGE - 1) % NSTAGE, (it + NSTAGE - 1) << 6);
            CP_WAIT(NSTAGE - 1);
        } else if (NSTAGE == 3 && it + 2 == nk) {
            CP_WAIT(1);
        } else {
            CP_WAIT(0);
        }
        __syncthreads();

        const uint32_t bAhi = sb + (uint32_t)((s * NBUF + 0) * BUFB);
        const uint32_t bAlo = sb + (uint32_t)((s * NBUF + 1) * BUFB);
        const uint32_t bBhi = sb + (uint32_t)((s * NBUF + NBUF - 1) * BUFB);

#pragma unroll
        for (int kk = 0; kk < 64; kk += 16) {
            uint32_t aH[2][4], aL[2][4];
#pragma unroll
            for (int mi = 0; mi < 2; ++mi) {
                uint32_t off = (uint32_t)((m0 + mi * 16 + a_row) * LDSE + kk + a_col) * 2;
                ldsm_x4(aH[mi], bAhi + off);
                if (NTERMS == 2) ldsm_x4(aL[mi], bAlo + off);
            }
#pragma unroll
            for (int nj = 0; nj < 4; ++nj) {
                uint32_t off = (uint32_t)((n0 + nj * 16 + b_row) * LDSE + kk + b_col) * 2;
                uint32_t bh[4];
                ldsm_x4(bh, bBhi + off);
#pragma unroll
                for (int mi = 0; mi < 2; ++mi) {
                    float* a0 = acc[mi][nj * 2];
                    float* a1 = acc[mi][nj * 2 + 1];
                    mma16816(a0, aH[mi], bh);
                    mma16816(a1, aH[mi], bh + 2);
                    if (NTERMS == 2) {
                        mma16816(a0, aL[mi], bh);
                        mma16816(a1, aL[mi], bh + 2);
                    }
                }
            }
        }
        __syncthreads();
    }

    // ---- epilogue ------------------------------------------------------------
    const int tr = lane >> 2;
    const int tc = (lane & 3) * 2;

    if (MODE == 1 || MODE == 4) {
#pragma unroll
        for (int mi = 0; mi < 2; ++mi)
#pragma unroll
            for (int nj = 0; nj < 8; ++nj) {
                int row = i0 + m0 + mi * 16 + tr;
                int col = j0 + n0 + nj * 8 + tc;
                size_t idx = (size_t)row * ldc + col;
                if (MODE == 1) {
                    uint32_t h, l;
                    split2h(acc[mi][nj][0], acc[mi][nj][1], h, l);
                    *reinterpret_cast<uint32_t*>(Chi + idx) = h;
                    *reinterpret_cast<uint32_t*>(Clo + idx) = l;
                    idx = (size_t)(row + 8) * ldc + col;
                    split2h(acc[mi][nj][2], acc[mi][nj][3], h, l);
                    *reinterpret_cast<uint32_t*>(Chi + idx) = h;
                    *reinterpret_cast<uint32_t*>(Clo + idx) = l;
                } else {
                    *reinterpret_cast<uint32_t*>(Chi + idx) =
                        pack2h(acc[mi][nj][0], acc[mi][nj][1]);
                    idx = (size_t)(row + 8) * ldc + col;
                    *reinterpret_cast<uint32_t*>(Chi + idx) =
                        pack2h(acc[mi][nj][2], acc[mi][nj][3]);
                }
            }
    } else if (MODE == 5) {
        // V tile [128 tok x 128 d] -> smem [d][tok] -> coalesced g_VThi writes
        uint16_t* vt = dsm;                           // [128][136] fp16 = 34816 B
#pragma unroll
        for (int mi = 0; mi < 2; ++mi)
#pragma unroll
            for (int nj = 0; nj < 8; ++nj) {
                int r = m0 + mi * 16 + tr;            // token row in tile
                int c = n0 + nj * 8 + tc;             // dim col in tile
                vt[(c    ) * 136 + r    ] = __half_as_ushort(h_hi(acc[mi][nj][0]));
                vt[(c + 1) * 136 + r    ] = __half_as_ushort(h_hi(acc[mi][nj][1]));
                vt[(c    ) * 136 + r + 8] = __half_as_ushort(h_hi(acc[mi][nj][2]));
                vt[(c + 1) * 136 + r + 8] = __half_as_ushort(h_hi(acc[mi][nj][3]));
            }
        __syncthreads();
        const int b = i0 >> 12;
        const int seqr = i0 & (SEQ - 1);
#pragma unroll
        for (int k = 0; k < 8; ++k) {                 // 2048 8-tok chunks
            int u = tid + k * 256;
            int d = u >> 4, tk = (u & 15) * 8;
            uint4 v = *reinterpret_cast<uint4*>(&vt[d * 136 + tk]);
            *reinterpret_cast<uint4*>(
                g_VThi + ((size_t)b * DIM + j0 + d) * SEQ + seqr + tk) = v;
        }
    } else if (MODE == 2) {
        float* red = reinterpret_cast<float*>(dsm);     // 128 rows x 2 n-warps
        const int nwid = wid >> 2;
#pragma unroll
        for (int mi = 0; mi < 2; ++mi) {
#pragma unroll
            for (int rp = 0; rp < 2; ++rp) {
                const int lrow = m0 + mi * 16 + tr + rp * 8;
                const int row  = i0 + lrow;
                float part = 0.f;
#pragma unroll
                for (int nj = 0; nj < 8; ++nj) {
                    int col = j0 + n0 + nj * 8 + tc;
                    float e0 = (col     <= row)
                        ? __expf(acc[mi][nj][rp * 2]     * SM_SCALE) * P_SCALE : 0.f;
                    float e1 = (col + 1 <= row)
                        ? __expf(acc[mi][nj][rp * 2 + 1] * SM_SCALE) * P_SCALE : 0.f;
                    size_t idx = (size_t)row * ldc + col;
                    *reinterpret_cast<uint32_t*>(Chi + idx) = pack2h(e0, e1);
                    part += e0 + e1;
                }
                part += __shfl_xor_sync(0xffffffffu, part, 1);
                part += __shfl_xor_sync(0xffffffffu, part, 2);
                if ((lane & 3) == 0) red[lrow * 2 + nwid] = part;
            }
        }
        __syncthreads();
        if (tid < 128) {
            float s = red[tid * 2] + red[tid * 2 + 1];
            g_partial[(size_t)(rs_off + i0 + tid) * 32 + (j0 >> 7)] = s;
        }
    } else {  // MODE 3: pv, normalize by row sums (both scaled by 1/64 -> cancels)
#pragma unroll
        for (int mi = 0; mi < 2; ++mi) {
            int row = i0 + m0 + mi * 16 + tr;
            float s0 = 1.0f / g_rowsum[rs_off + row];
            float s1 = 1.0f / g_rowsum[rs_off + row + 8];
#pragma unroll
            for (int nj = 0; nj < 8; ++nj) {
                int col = j0 + n0 + nj * 8 + tc;
                *reinterpret_cast<float2*>(C + (size_t)row * ldc + col) =
                    make_float2(acc[mi][nj][0] * s0, acc[mi][nj][1] * s0);
                *reinterpret_cast<float2*>(C + (size_t)(row + 8) * ldc + col) =
                    make_float2(acc[mi][nj][2] * s1, acc[mi][nj][3] * s1);
            }
        }
    }
}

// ---------------- GEMM stage kernels ------------------------------------------
__global__ void __launch_bounds__(256, 2)
proj_q_tc()
{
    gemm_pipe<1, 2>(g_Xhi, g_Xlo, DIM, g_WThi, DIM,
                    nullptr, g_Qhi, g_Qlo, DIM,
                    blockIdx.y * 128, blockIdx.x * 128, DIM, 0);
}

__global__ void __launch_bounds__(256, 2)
proj_k_tc()
{
    gemm_pipe<4, 1>(g_Xhi, nullptr, DIM, g_WThi + (size_t)DIM * DIM, DIM,
                    nullptr, g_Khi, nullptr, DIM,
                    blockIdx.y * 128, blockIdx.x * 128, DIM, 0);
}

__global__ void __launch_bounds__(256, 2)
proj_v_tc()
{
    gemm_pipe<5, 1>(g_Xhi, nullptr, DIM, g_WThi + 2ull * DIM * DIM, DIM,
                    nullptr, nullptr, nullptr, DIM,
                    blockIdx.y * 128, blockIdx.x * 128, DIM, 0);
}

__global__ void __launch_bounds__(256, 2)
scores_tc()
{
    // triangular tile decode: t -> (i >= j)
    const int t = blockIdx.x;
    int i = (int)((sqrtf(8.0f * t + 1.0f) - 1.0f) * 0.5f);
    while ((i + 1) * (i + 2) / 2 <= t) ++i;
    while (i * (i + 1) / 2 > t) --i;
    const int j = t - i * (i + 1) / 2;
    const int i0 = i * 128, j0 = j * 128;

    const size_t off = (size_t)blockIdx.z * SEQ * DIM;
    __half* Ch = g_Phi + (size_t)blockIdx.z * SEQ * SEQ;
    gemm_pipe<2, 2>(g_Qhi + off, g_Qlo + off, DIM, g_Khi + off, DIM,
                    nullptr, Ch, nullptr, SEQ, i0, j0, DIM, blockIdx.z * SEQ);
}

__global__ void __launch_bounds__(256, 2)
pv_tc(float* __restrict__ out)
{
    const int i0 = blockIdx.y * 128, j0 = blockIdx.x * 128;
    const size_t poff = (size_t)blockIdx.z * SEQ * SEQ;
    const size_t voff = (size_t)blockIdx.z * DIM * SEQ;
    float* C = out + (size_t)blockIdx.z * SEQ * DIM;
    gemm_pipe<3, 1>(g_Phi + poff, nullptr, SEQ, g_VThi + voff, SEQ,
                    C, nullptr, nullptr, DIM, i0, j0, i0 + 128, blockIdx.z * SEQ);
}

// ---------------- rowsum reduce (deterministic) ---------------------------------
__global__ void __launch_bounds__(256)
reduce_rowsum()
{
    const int i = blockIdx.x * 256 + threadIdx.x;
    const int q = i & (SEQ - 1);
    const int nt = (q >> 7) + 1;
    const float* p = g_partial + (size_t)i * 32;
    float s = 0.f;
    for (int t = 0; t < nt; ++t) s += p[t];
    g_rowsum[i] = s;
}

// ---------------- conversion / transpose kernels -------------------------------
__global__ void conv_x(const float* __restrict__ X)
{
    size_t i = (size_t)blockIdx.x * blockDim.x + threadIdx.x;
    const size_t n4 = (size_t)NTOK * DIM / 4;
    for (; i < n4; i += (size_t)gridDim.x * blockDim.x) {
        float4 v = reinterpret_cast<const float4*>(X)[i];
        uint32_t h0, l0, h1, l1;
        split2h(v.x, v.y, h0, l0);
        split2h(v.z, v.w, h1, l1);
        reinterpret_cast<uint2*>(g_Xhi)[i] = make_uint2(h0, h1);
        reinterpret_cast<uint2*>(g_Xlo)[i] = make_uint2(l0, l1);
    }
}

__global__ void transpose_w(const float* __restrict__ Wq,
                            const float* __restrict__ Wk,
                            const float* __restrict__ Wv)
{
    const float* src = (blockIdx.z == 0) ? Wq : (blockIdx.z == 1) ? Wk : Wv;
    __half* dh = g_WThi + (size_t)blockIdx.z * DIM * DIM;
    __shared__ float t[32][33];
    const int bx = blockIdx.x * 32, by = blockIdx.y * 32;
    const int tx = threadIdx.x, ty = threadIdx.y;
#pragma unroll
    for (int j = 0; j < 32; j += 8)
        t[ty + j][tx] = src[(size_t)(by + ty + j) * DIM + bx + tx];
    __syncthreads();
#pragma unroll
    for (int j = 0; j < 32; j += 8)
        dh[(size_t)(bx + ty + j) * DIM + by + tx] = h_hi(t[tx][ty + j]);
}

// ---------------- launch ---------------------------------------------------------
extern "C" void kernel_launch(void* const* d_in, const int* in_sizes, int n_in,
                              void* d_out, int out_size)
{
    const float* x  = (const float*)d_in[0];
    const float* Wq = (const float*)d_in[1];
    const float* Wk = (const float*)d_in[2];
    const float* Wv = (const float*)d_in[3];
    float* out = (float*)d_out;

    cudaFuncSetAttribute(proj_q_tc, cudaFuncAttributeMaxDynamicSharedMemorySize, SMEM_BYTES);
    cudaFuncSetAttribute(proj_k_tc, cudaFuncAttributeMaxDynamicSharedMemorySize, SMEM_BYTES);
    cudaFuncSetAttribute(proj_v_tc, cudaFuncAttributeMaxDynamicSharedMemorySize, SMEM_BYTES);
    cudaFuncSetAttribute(scores_tc, cudaFuncAttributeMaxDynamicSharedMemorySize, SMEM_BYTES);
    cudaFuncSetAttribute(pv_tc,     cudaFuncAttributeMaxDynamicSharedMemorySize, SMEM_BYTES);

    dim3 t32(32, 8);
    conv_x<<<512, 256>>>(x);
    transpose_w<<<dim3(DIM / 32, DIM / 32, 3), t32>>>(Wq, Wk, Wv);
    proj_q_tc<<<dim3(DIM / 128, NTOK / 128), 256, SMEM_BYTES>>>();
    proj_k_tc<<<dim3(DIM / 128, NTOK / 128), 256, SMEM_BYTES>>>();
    proj_v_tc<<<dim3(DIM / 128, NTOK / 128), 256, SMEM_BYTES>>>();
    scores_tc<<<dim3(528, 1, BATCH), 256, SMEM_BYTES>>>();
    reduce_rowsum<<<NTOK / 256, 256>>>();
    pv_tc<<<dim3(DIM / 128, SEQ / 128, BATCH), 256, SMEM_BYTES>>>(out);
}

// round 15
// speedup vs baseline: 1.2356x; 1.1774x over previous
#include <cuda_runtime.h>
#include <cuda_fp16.h>
#include <cstdint>

#define BATCH 4
#define SEQ   4096
#define DIM   768
#define NTOK  (BATCH*SEQ)

// ---------------- scratch (__device__ globals: allocation-free rule) --------
__device__ __half g_Xhi [(size_t)NTOK * DIM];
__device__ __half g_Xlo [(size_t)NTOK * DIM];
__device__ __half g_WThi[3ull * DIM * DIM];               // B side: hi only
__device__ __half g_Qhi [(size_t)NTOK * DIM];             // fp16 only (A side, scores)
__device__ __half g_Khi [(size_t)NTOK * DIM];             // fp16 only (B side)
__device__ __half g_VThi[(size_t)BATCH * DIM * SEQ];      // V^T (written by proj_v epi)
__device__ __half g_Phi [(size_t)BATCH * SEQ * SEQ];      // exp(scores)/64, fp16
__device__ float g_partial[(size_t)NTOK * 32];            // per-(row,tile) sums
__device__ float g_rowsum [(size_t)NTOK];                 // final row sums

// ---------------- PTX helpers (arch-agnostic, sm_80-class) ------------------
__device__ __forceinline__ uint32_t smem_u32(const void* p) {
    uint32_t a;
    asm("{ .reg .u64 t; cvta.to.shared.u64 t, %1; cvt.u32.u64 %0, t; }"
        : "=r"(a) : "l"(p));
    return a;
}
__device__ __forceinline__ void cp16(uint32_t dst, const void* src) {
    asm volatile("cp.async.cg.shared.global [%0], [%1], 16;"
                 :: "r"(dst), "l"(src) : "memory");
}
#define CP_COMMIT() asm volatile("cp.async.commit_group;" ::: "memory")
#define CP_WAIT(N)  asm volatile("cp.async.wait_group %0;" :: "n"(N) : "memory")

__device__ __forceinline__ void ldsm_x4(uint32_t* r, uint32_t addr) {
    asm volatile("ldmatrix.sync.aligned.m8n8.x4.shared.b16 {%0,%1,%2,%3}, [%4];"
                 : "=r"(r[0]), "=r"(r[1]), "=r"(r[2]), "=r"(r[3]) : "r"(addr));
}
__device__ __forceinline__ void mma16816(float* d, const uint32_t* a, const uint32_t* b) {
    asm volatile(
        "mma.sync.aligned.m16n8k16.row.col.f32.f16.f16.f32 "
        "{%0,%1,%2,%3}, {%4,%5,%6,%7}, {%8,%9}, {%0,%1,%2,%3};"
        : "+f"(d[0]), "+f"(d[1]), "+f"(d[2]), "+f"(d[3])
        : "r"(a[0]), "r"(a[1]), "r"(a[2]), "r"(a[3]), "r"(b[0]), "r"(b[1]));
}

__device__ __forceinline__ void split2h(float a, float b, uint32_t& h, uint32_t& l) {
    __half2 hv = __floats2half2_rn(a, b);
    float2 f = __half22float2(hv);
    __half2 lv = __floats2half2_rn(a - f.x, b - f.y);
    h = *reinterpret_cast<uint32_t*>(&hv);
    l = *reinterpret_cast<uint32_t*>(&lv);
}
__device__ __forceinline__ uint32_t pack2h(float a, float b) {
    __half2 hv = __floats2half2_rn(a, b);
    return *reinterpret_cast<uint32_t*>(&hv);
}
__device__ __forceinline__ __half h_hi(float v) { return __float2half_rn(v); }

// ---------------- pipelined GEMM core (R12 shape: proven optimum) -------------
// C[128,128] = (Ahi[+Alo])[128,K] * Bhi[128,K]^T, fp16 MMA x NTERMS, fp32 accum.
// 256 threads, 4(m) x 2(n) warps, warp tile 32x64, k-step 64, 2 CTAs/SM.
// 2-term: 2-stage x 3 bufs; 1-term: 3-stage x 2 bufs (both 110.6 KB).
#define LDSE 72
#define BUFB (128 * LDSE * 2)        // 18432 B
#define SMEM_BYTES 110592

#define SM_SCALE 0.03608439182435161f   // 1/sqrt(768)
#define P_SCALE  0.015625f              // store exp/64

// MODE 4: fp16 Chi only (proj Q/K).
// MODE 5: V -> g_VThi transposed via smem (proj V).
// MODE 2: exp/64 + causal mask + row partial sums; fp16 out (scores).
// MODE 3: fp32 C scaled by 1/g_rowsum[row] (pv).
template <int MODE, int NTERMS>
__device__ __forceinline__ void gemm_pipe(
    const __half* __restrict__ Ahi, const __half* __restrict__ Alo, int lda,
    const __half* __restrict__ Bhi, int ldb,
    float* __restrict__ C, __half* __restrict__ Chi,
    int ldc, int i0, int j0, int K, int rs_off)
{
    extern __shared__ __align__(16) uint16_t dsm[];
    const uint32_t sb = smem_u32(dsm);

    const int tid  = threadIdx.x;
    const int wid  = tid >> 5;
    const int lane = tid & 31;
    const int m0 = (wid & 3) * 32;
    const int n0 = (wid >> 2) * 64;

    const int a_row = lane & 15;
    const int a_col = (lane >> 4) * 8;
    const int b_row = ((lane >> 4) & 1) * 8 + (lane & 7);
    const int b_col = ((lane >> 3) & 1) * 8;

    constexpr int NBUF   = NTERMS + 1;
    constexpr int NSTAGE = (NTERMS == 2) ? 2 : 3;
    const __half* gsrc[3] = {Ahi, (NTERMS == 2) ? Alo : Bhi, Bhi};
    const int glda[3] = {lda, (NTERMS == 2) ? lda : ldb, ldb};
    const int grow[3] = {i0, (NTERMS == 2) ? i0 : j0, j0};

    const int nk = K >> 6;

    auto stage = [&](int s, int kt) {
#pragma unroll
        for (int b = 0; b < NBUF; ++b) {
            uint32_t base = sb + (uint32_t)((s * NBUF + b) * BUFB);
            const __half* g = gsrc[b];
#pragma unroll
            for (int k = 0; k < 4; ++k) {
                int u = tid + k * 256;
                int r = u >> 3, c = (u & 7) * 8;
                cp16(base + (uint32_t)(r * LDSE + c) * 2,
                     g + (size_t)(grow[b] + r) * glda[b] + kt + c);
            }
        }
        CP_COMMIT();
    };

    float acc[2][8][4] = {};

    stage(0, 0);
    if (NSTAGE == 3 && nk > 1) stage(1, 64);
    for (int it = 0; it < nk; ++it) {
        const int s = it % NSTAGE;
        if (it + NSTAGE - 1 < nk) {
            stage((it + NSTAGE - 1) % NSTAGE, (it + NSTAGE - 1) << 6);
            CP_WAIT(NSTAGE - 1);
        } else if (NSTAGE == 3 && it + 2 == nk) {
            CP_WAIT(1);
        } else {
            CP_WAIT(0);
        }
        __syncthreads();

        const uint32_t bAhi = sb + (uint32_t)((s * NBUF + 0) * BUFB);
        const uint32_t bAlo = sb + (uint32_t)((s * NBUF + 1) * BUFB);
        const uint32_t bBhi = sb + (uint32_t)((s * NBUF + NBUF - 1) * BUFB);

#pragma unroll
        for (int kk = 0; kk < 64; kk += 16) {
            uint32_t aH[2][4], aL[2][4];
#pragma unroll
            for (int mi = 0; mi < 2; ++mi) {
                uint32_t off = (uint32_t)((m0 + mi * 16 + a_row) * LDSE + kk + a_col) * 2;
                ldsm_x4(aH[mi], bAhi + off);
                if (NTERMS == 2) ldsm_x4(aL[mi], bAlo + off);
            }
#pragma unroll
            for (int nj = 0; nj < 4; ++nj) {
                uint32_t off = (uint32_t)((n0 + nj * 16 + b_row) * LDSE + kk + b_col) * 2;
                uint32_t bh[4];
                ldsm_x4(bh, bBhi + off);
#pragma unroll
                for (int mi = 0; mi < 2; ++mi) {
                    float* a0 = acc[mi][nj * 2];
                    float* a1 = acc[mi][nj * 2 + 1];
                    mma16816(a0, aH[mi], bh);
                    mma16816(a1, aH[mi], bh + 2);
                    if (NTERMS == 2) {
                        mma16816(a0, aL[mi], bh);
                        mma16816(a1, aL[mi], bh + 2);
                    }
                }
            }
        }
        __syncthreads();
    }

    // ---- epilogue ------------------------------------------------------------
    const int tr = lane >> 2;
    const int tc = (lane & 3) * 2;

    if (MODE == 4) {
#pragma unroll
        for (int mi = 0; mi < 2; ++mi)
#pragma unroll
            for (int nj = 0; nj < 8; ++nj) {
                int row = i0 + m0 + mi * 16 + tr;
                int col = j0 + n0 + nj * 8 + tc;
                *reinterpret_cast<uint32_t*>(Chi + (size_t)row * ldc + col) =
                    pack2h(acc[mi][nj][0], acc[mi][nj][1]);
                *reinterpret_cast<uint32_t*>(Chi + (size_t)(row + 8) * ldc + col) =
                    pack2h(acc[mi][nj][2], acc[mi][nj][3]);
            }
    } else if (MODE == 5) {
        // V tile [128 tok x 128 d] -> smem [d][tok] -> coalesced g_VThi writes
        uint16_t* vt = dsm;                           // [128][136] fp16 = 34816 B
#pragma unroll
        for (int mi = 0; mi < 2; ++mi)
#pragma unroll
            for (int nj = 0; nj < 8; ++nj) {
                int r = m0 + mi * 16 + tr;
                int c = n0 + nj * 8 + tc;
                vt[(c    ) * 136 + r    ] = __half_as_ushort(h_hi(acc[mi][nj][0]));
                vt[(c + 1) * 136 + r    ] = __half_as_ushort(h_hi(acc[mi][nj][1]));
                vt[(c    ) * 136 + r + 8] = __half_as_ushort(h_hi(acc[mi][nj][2]));
                vt[(c + 1) * 136 + r + 8] = __half_as_ushort(h_hi(acc[mi][nj][3]));
            }
        __syncthreads();
        const int b = i0 >> 12;
        const int seqr = i0 & (SEQ - 1);
#pragma unroll
        for (int k = 0; k < 8; ++k) {
            int u = tid + k * 256;
            int d = u >> 4, tk = (u & 15) * 8;
            uint4 v = *reinterpret_cast<uint4*>(&vt[d * 136 + tk]);
            *reinterpret_cast<uint4*>(
                g_VThi + ((size_t)b * DIM + j0 + d) * SEQ + seqr + tk) = v;
        }
    } else if (MODE == 2) {
        float* red = reinterpret_cast<float*>(dsm);     // 128 rows x 2 n-warps
        const int nwid = wid >> 2;
#pragma unroll
        for (int mi = 0; mi < 2; ++mi) {
#pragma unroll
            for (int rp = 0; rp < 2; ++rp) {
                const int lrow = m0 + mi * 16 + tr + rp * 8;
                const int row  = i0 + lrow;
                float part = 0.f;
#pragma unroll
                for (int nj = 0; nj < 8; ++nj) {
                    int col = j0 + n0 + nj * 8 + tc;
                    float e0 = (col     <= row)
                        ? __expf(acc[mi][nj][rp * 2]     * SM_SCALE) * P_SCALE : 0.f;
                    float e1 = (col + 1 <= row)
                        ? __expf(acc[mi][nj][rp * 2 + 1] * SM_SCALE) * P_SCALE : 0.f;
                    size_t idx = (size_t)row * ldc + col;
                    *reinterpret_cast<uint32_t*>(Chi + idx) = pack2h(e0, e1);
                    part += e0 + e1;
                }
                part += __shfl_xor_sync(0xffffffffu, part, 1);
                part += __shfl_xor_sync(0xffffffffu, part, 2);
                if ((lane & 3) == 0) red[lrow * 2 + nwid] = part;
            }
        }
        __syncthreads();
        if (tid < 128) {
            float s = red[tid * 2] + red[tid * 2 + 1];
            g_partial[(size_t)(rs_off + i0 + tid) * 32 + (j0 >> 7)] = s;
        }
    } else {  // MODE 3: pv, normalize by row sums (both scaled by 1/64 -> cancels)
#pragma unroll
        for (int mi = 0; mi < 2; ++mi) {
            int row = i0 + m0 + mi * 16 + tr;
            float s0 = 1.0f / g_rowsum[rs_off + row];
            float s1 = 1.0f / g_rowsum[rs_off + row + 8];
#pragma unroll
            for (int nj = 0; nj < 8; ++nj) {
                int col = j0 + n0 + nj * 8 + tc;
                *reinterpret_cast<float2*>(C + (size_t)row * ldc + col) =
                    make_float2(acc[mi][nj][0] * s0, acc[mi][nj][1] * s0);
                *reinterpret_cast<float2*>(C + (size_t)(row + 8) * ldc + col) =
                    make_float2(acc[mi][nj][2] * s1, acc[mi][nj][3] * s1);
            }
        }
    }
}

// ---------------- GEMM stage kernels ------------------------------------------
__global__ void __launch_bounds__(256, 2)
proj_q_tc()   // 2-term X input (accuracy hedge), fp16 single output
{
    gemm_pipe<4, 2>(g_Xhi, g_Xlo, DIM, g_WThi, DIM,
                    nullptr, g_Qhi, DIM,
                    blockIdx.y * 128, blockIdx.x * 128, DIM, 0);
}

__global__ void __launch_bounds__(256, 2)
proj_k_tc()
{
    gemm_pipe<4, 1>(g_Xhi, nullptr, DIM, g_WThi + (size_t)DIM * DIM, DIM,
                    nullptr, g_Khi, DIM,
                    blockIdx.y * 128, blockIdx.x * 128, DIM, 0);
}

__global__ void __launch_bounds__(256, 2)
proj_v_tc()
{
    gemm_pipe<5, 1>(g_Xhi, nullptr, DIM, g_WThi + 2ull * DIM * DIM, DIM,
                    nullptr, nullptr, DIM,
                    blockIdx.y * 128, blockIdx.x * 128, DIM, 0);
}

__global__ void __launch_bounds__(256, 2)
scores_tc()   // 1-term now: Qhi * Khi^T
{
    // triangular tile decode: t -> (i >= j)
    const int t = blockIdx.x;
    int i = (int)((sqrtf(8.0f * t + 1.0f) - 1.0f) * 0.5f);
    while ((i + 1) * (i + 2) / 2 <= t) ++i;
    while (i * (i + 1) / 2 > t) --i;
    const int j = t - i * (i + 1) / 2;
    const int i0 = i * 128, j0 = j * 128;

    const size_t off = (size_t)blockIdx.z * SEQ * DIM;
    __half* Ch = g_Phi + (size_t)blockIdx.z * SEQ * SEQ;
    gemm_pipe<2, 1>(g_Qhi + off, nullptr, DIM, g_Khi + off, DIM,
                    nullptr, Ch, SEQ, i0, j0, DIM, blockIdx.z * SEQ);
}

__global__ void __launch_bounds__(256, 2)
pv_tc(float* __restrict__ out)
{
    const int i0 = blockIdx.y * 128, j0 = blockIdx.x * 128;
    const size_t poff = (size_t)blockIdx.z * SEQ * SEQ;
    const size_t voff = (size_t)blockIdx.z * DIM * SEQ;
    float* C = out + (size_t)blockIdx.z * SEQ * DIM;
    gemm_pipe<3, 1>(g_Phi + poff, nullptr, SEQ, g_VThi + voff, SEQ,
                    C, nullptr, DIM, i0, j0, i0 + 128, blockIdx.z * SEQ);
}

// ---------------- rowsum reduce (deterministic) ---------------------------------
__global__ void __launch_bounds__(256)
reduce_rowsum()
{
    const int i = blockIdx.x * 256 + threadIdx.x;
    const int q = i & (SEQ - 1);
    const int nt = (q >> 7) + 1;
    const float* p = g_partial + (size_t)i * 32;
    float s = 0.f;
    for (int t = 0; t < nt; ++t) s += p[t];
    g_rowsum[i] = s;
}

// ---------------- conversion / transpose kernels -------------------------------
__global__ void conv_x(const float* __restrict__ X)
{
    size_t i = (size_t)blockIdx.x * blockDim.x + threadIdx.x;
    const size_t n4 = (size_t)NTOK * DIM / 4;
    for (; i < n4; i += (size_t)gridDim.x * blockDim.x) {
        float4 v = reinterpret_cast<const float4*>(X)[i];
        uint32_t h0, l0, h1, l1;
        split2h(v.x, v.y, h0, l0);
        split2h(v.z, v.w, h1, l1);
        reinterpret_cast<uint2*>(g_Xhi)[i] = make_uint2(h0, h1);
        reinterpret_cast<uint2*>(g_Xlo)[i] = make_uint2(l0, l1);
    }
}

__global__ void transpose_w(const float* __restrict__ Wq,
                            const float* __restrict__ Wk,
                            const float* __restrict__ Wv)
{
    const float* src = (blockIdx.z == 0) ? Wq : (blockIdx.z == 1) ? Wk : Wv;
    __half* dh = g_WThi + (size_t)blockIdx.z * DIM * DIM;
    __shared__ float t[32][33];
    const int bx = blockIdx.x * 32, by = blockIdx.y * 32;
    const int tx = threadIdx.x, ty = threadIdx.y;
#pragma unroll
    for (int j = 0; j < 32; j += 8)
        t[ty + j][tx] = src[(size_t)(by + ty + j) * DIM + bx + tx];
    __syncthreads();
#pragma unroll
    for (int j = 0; j < 32; j += 8)
        dh[(size_t)(bx + ty + j) * DIM + by + tx] = h_hi(t[tx][ty + j]);
}

// ---------------- launch ---------------------------------------------------------
extern "C" void kernel_launch(void* const* d_in, const int* in_sizes, int n_in,
                              void* d_out, int out_size)
{
    const float* x  = (const float*)d_in[0];
    const float* Wq = (const float*)d_in[1];
    const float* Wk = (const float*)d_in[2];
    const float* Wv = (const float*)d_in[3];
    float* out = (float*)d_out;

    cudaFuncSetAttribute(proj_q_tc, cudaFuncAttributeMaxDynamicSharedMemorySize, SMEM_BYTES);
    cudaFuncSetAttribute(proj_k_tc, cudaFuncAttributeMaxDynamicSharedMemorySize, SMEM_BYTES);
    cudaFuncSetAttribute(proj_v_tc, cudaFuncAttributeMaxDynamicSharedMemorySize, SMEM_BYTES);
    cudaFuncSetAttribute(scores_tc, cudaFuncAttributeMaxDynamicSharedMemorySize, SMEM_BYTES);
    cudaFuncSetAttribute(pv_tc,     cudaFuncAttributeMaxDynamicSharedMemorySize, SMEM_BYTES);

    dim3 t32(32, 8);
    conv_x<<<512, 256>>>(x);
    transpose_w<<<dim3(DIM / 32, DIM / 32, 3), t32>>>(Wq, Wk, Wv);
    proj_q_tc<<<dim3(DIM / 128, NTOK / 128), 256, SMEM_BYTES>>>();
    proj_k_tc<<<dim3(DIM / 128, NTOK / 128), 256, SMEM_BYTES>>>();
    proj_v_tc<<<dim3(DIM / 128, NTOK / 128), 256, SMEM_BYTES>>>();
    scores_tc<<<dim3(528, 1, BATCH), 256, SMEM_BYTES>>>();
    reduce_rowsum<<<NTOK / 256, 256>>>();
    pv_tc<<<dim3(DIM / 128, SEQ / 128, BATCH), 256, SMEM_BYTES>>>(out);
}

// round 16
// speedup vs baseline: 1.4046x; 1.1368x over previous
#include <cuda_runtime.h>
#include <cuda_fp16.h>
#include <cstdint>

#define BATCH 4
#define SEQ   4096
#define DIM   768
#define NTOK  (BATCH*SEQ)

// ---------------- scratch (__device__ globals: allocation-free rule) --------
__device__ __half g_Xhi [(size_t)NTOK * DIM];             // fp16 X
__device__ __half g_WThi[3ull * DIM * DIM];               // W^T fp16
__device__ __half g_Qhi [(size_t)NTOK * DIM];
__device__ __half g_Khi [(size_t)NTOK * DIM];
__device__ __half g_VThi[(size_t)BATCH * DIM * SEQ];      // V^T (written by proj epi)
__device__ __half g_Phi [(size_t)BATCH * SEQ * SEQ];      // exp(scores)/64, fp16
__device__ float g_partial[(size_t)NTOK * 32];            // per-(row,tile) sums
__device__ float g_rowsum [(size_t)NTOK];                 // final row sums

// ---------------- PTX helpers (arch-agnostic, sm_80-class) ------------------
__device__ __forceinline__ uint32_t smem_u32(const void* p) {
    uint32_t a;
    asm("{ .reg .u64 t; cvta.to.shared.u64 t, %1; cvt.u32.u64 %0, t; }"
        : "=r"(a) : "l"(p));
    return a;
}
__device__ __forceinline__ void cp16(uint32_t dst, const void* src) {
    asm volatile("cp.async.cg.shared.global [%0], [%1], 16;"
                 :: "r"(dst), "l"(src) : "memory");
}
#define CP_COMMIT() asm volatile("cp.async.commit_group;" ::: "memory")
#define CP_WAIT(N)  asm volatile("cp.async.wait_group %0;" :: "n"(N) : "memory")

__device__ __forceinline__ void ldsm_x4(uint32_t* r, uint32_t addr) {
    asm volatile("ldmatrix.sync.aligned.m8n8.x4.shared.b16 {%0,%1,%2,%3}, [%4];"
                 : "=r"(r[0]), "=r"(r[1]), "=r"(r[2]), "=r"(r[3]) : "r"(addr));
}
__device__ __forceinline__ void mma16816(float* d, const uint32_t* a, const uint32_t* b) {
    asm volatile(
        "mma.sync.aligned.m16n8k16.row.col.f32.f16.f16.f32 "
        "{%0,%1,%2,%3}, {%4,%5,%6,%7}, {%8,%9}, {%0,%1,%2,%3};"
        : "+f"(d[0]), "+f"(d[1]), "+f"(d[2]), "+f"(d[3])
        : "r"(a[0]), "r"(a[1]), "r"(a[2]), "r"(a[3]), "r"(b[0]), "r"(b[1]));
}

__device__ __forceinline__ uint32_t pack2h(float a, float b) {
    __half2 hv = __floats2half2_rn(a, b);
    return *reinterpret_cast<uint32_t*>(&hv);
}
__device__ __forceinline__ __half h_hi(float v) { return __float2half_rn(v); }

// ---------------- pipelined GEMM core (R12 shape: proven optimum) -------------
// C[128,128] = Ahi[128,K] * Bhi[128,K]^T, fp16 MMA, fp32 accum.
// 256 threads, 4(m) x 2(n) warps, warp tile 32x64, k-step 64, 2 CTAs/SM.
// 1-term: 3-stage x 2 buffers (110.6 KB/CTA).
#define LDSE 72
#define BUFB (128 * LDSE * 2)        // 18432 B
#define SMEM_BYTES 110592

#define SM_SCALE 0.03608439182435161f   // 1/sqrt(768)
#define P_SCALE  0.015625f              // store exp/64

// MODE 4: fp16 Chi (proj Q/K).
// MODE 5: V -> g_VThi transposed via smem (proj V).
// MODE 2: exp/64 + causal mask + row partial sums; fp16 out (scores).
// MODE 3: fp32 C scaled by 1/g_rowsum[row] (pv).
template <int MODE>
__device__ __forceinline__ void gemm_pipe(
    const __half* __restrict__ Ahi, int lda,
    const __half* __restrict__ Bhi, int ldb,
    float* __restrict__ C, __half* __restrict__ Chi,
    int ldc, int i0, int j0, int K, int rs_off)
{
    extern __shared__ __align__(16) uint16_t dsm[];
    const uint32_t sb = smem_u32(dsm);

    const int tid  = threadIdx.x;
    const int wid  = tid >> 5;
    const int lane = tid & 31;
    const int m0 = (wid & 3) * 32;
    const int n0 = (wid >> 2) * 64;

    const int a_row = lane & 15;
    const int a_col = (lane >> 4) * 8;
    const int b_row = ((lane >> 4) & 1) * 8 + (lane & 7);
    const int b_col = ((lane >> 3) & 1) * 8;

    const __half* gsrc[2] = {Ahi, Bhi};
    const int glda[2] = {lda, ldb};
    const int grow[2] = {i0, j0};

    const int nk = K >> 6;

    auto stage = [&](int s, int kt) {
#pragma unroll
        for (int b = 0; b < 2; ++b) {
            uint32_t base = sb + (uint32_t)((s * 2 + b) * BUFB);
            const __half* g = gsrc[b];
#pragma unroll
            for (int k = 0; k < 4; ++k) {
                int u = tid + k * 256;
                int r = u >> 3, c = (u & 7) * 8;
                cp16(base + (uint32_t)(r * LDSE + c) * 2,
                     g + (size_t)(grow[b] + r) * glda[b] + kt + c);
            }
        }
        CP_COMMIT();
    };

    float acc[2][8][4] = {};

    stage(0, 0);
    if (nk > 1) stage(1, 64);
    for (int it = 0; it < nk; ++it) {
        const int s = it % 3;
        if (it + 2 < nk)       { stage((it + 2) % 3, (it + 2) << 6); CP_WAIT(2); }
        else if (it + 2 == nk) { CP_WAIT(1); }
        else                   { CP_WAIT(0); }
        __syncthreads();

        const uint32_t bAhi = sb + (uint32_t)((s * 2 + 0) * BUFB);
        const uint32_t bBhi = sb + (uint32_t)((s * 2 + 1) * BUFB);

#pragma unroll
        for (int kk = 0; kk < 64; kk += 16) {
            uint32_t aH[2][4];
#pragma unroll
            for (int mi = 0; mi < 2; ++mi) {
                uint32_t off = (uint32_t)((m0 + mi * 16 + a_row) * LDSE + kk + a_col) * 2;
                ldsm_x4(aH[mi], bAhi + off);
            }
#pragma unroll
            for (int nj = 0; nj < 4; ++nj) {
                uint32_t off = (uint32_t)((n0 + nj * 16 + b_row) * LDSE + kk + b_col) * 2;
                uint32_t bh[4];
                ldsm_x4(bh, bBhi + off);
#pragma unroll
                for (int mi = 0; mi < 2; ++mi) {
                    mma16816(acc[mi][nj * 2],     aH[mi], bh);
                    mma16816(acc[mi][nj * 2 + 1], aH[mi], bh + 2);
                }
            }
        }
        __syncthreads();
    }

    // ---- epilogue ------------------------------------------------------------
    const int tr = lane >> 2;
    const int tc = (lane & 3) * 2;

    if (MODE == 4) {
#pragma unroll
        for (int mi = 0; mi < 2; ++mi)
#pragma unroll
            for (int nj = 0; nj < 8; ++nj) {
                int row = i0 + m0 + mi * 16 + tr;
                int col = j0 + n0 + nj * 8 + tc;
                *reinterpret_cast<uint32_t*>(Chi + (size_t)row * ldc + col) =
                    pack2h(acc[mi][nj][0], acc[mi][nj][1]);
                *reinterpret_cast<uint32_t*>(Chi + (size_t)(row + 8) * ldc + col) =
                    pack2h(acc[mi][nj][2], acc[mi][nj][3]);
            }
    } else if (MODE == 5) {
        // V tile [128 tok x 128 d] -> smem [d][tok] -> coalesced g_VThi writes
        uint16_t* vt = dsm;                           // [128][136] fp16 = 34816 B
#pragma unroll
        for (int mi = 0; mi < 2; ++mi)
#pragma unroll
            for (int nj = 0; nj < 8; ++nj) {
                int r = m0 + mi * 16 + tr;
                int c = n0 + nj * 8 + tc;
                vt[(c    ) * 136 + r    ] = __half_as_ushort(h_hi(acc[mi][nj][0]));
                vt[(c + 1) * 136 + r    ] = __half_as_ushort(h_hi(acc[mi][nj][1]));
                vt[(c    ) * 136 + r + 8] = __half_as_ushort(h_hi(acc[mi][nj][2]));
                vt[(c + 1) * 136 + r + 8] = __half_as_ushort(h_hi(acc[mi][nj][3]));
            }
        __syncthreads();
        const int b = i0 >> 12;
        const int seqr = i0 & (SEQ - 1);
#pragma unroll
        for (int k = 0; k < 8; ++k) {
            int u = tid + k * 256;
            int d = u >> 4, tk = (u & 15) * 8;
            uint4 v = *reinterpret_cast<uint4*>(&vt[d * 136 + tk]);
            *reinterpret_cast<uint4*>(
                g_VThi + ((size_t)b * DIM + j0 + d) * SEQ + seqr + tk) = v;
        }
    } else if (MODE == 2) {
        float* red = reinterpret_cast<float*>(dsm);     // 128 rows x 2 n-warps
        const int nwid = wid >> 2;
#pragma unroll
        for (int mi = 0; mi < 2; ++mi) {
#pragma unroll
            for (int rp = 0; rp < 2; ++rp) {
                const int lrow = m0 + mi * 16 + tr + rp * 8;
                const int row  = i0 + lrow;
                float part = 0.f;
#pragma unroll
                for (int nj = 0; nj < 8; ++nj) {
                    int col = j0 + n0 + nj * 8 + tc;
                    float e0 = (col     <= row)
                        ? __expf(acc[mi][nj][rp * 2]     * SM_SCALE) * P_SCALE : 0.f;
                    float e1 = (col + 1 <= row)
                        ? __expf(acc[mi][nj][rp * 2 + 1] * SM_SCALE) * P_SCALE : 0.f;
                    size_t idx = (size_t)row * ldc + col;
                    *reinterpret_cast<uint32_t*>(Chi + idx) = pack2h(e0, e1);
                    part += e0 + e1;
                }
                part += __shfl_xor_sync(0xffffffffu, part, 1);
                part += __shfl_xor_sync(0xffffffffu, part, 2);
                if ((lane & 3) == 0) red[lrow * 2 + nwid] = part;
            }
        }
        __syncthreads();
        if (tid < 128) {
            float s = red[tid * 2] + red[tid * 2 + 1];
            g_partial[(size_t)(rs_off + i0 + tid) * 32 + (j0 >> 7)] = s;
        }
    } else {  // MODE 3: pv, normalize by row sums (both scaled by 1/64 -> cancels)
#pragma unroll
        for (int mi = 0; mi < 2; ++mi) {
            int row = i0 + m0 + mi * 16 + tr;
            float s0 = 1.0f / g_rowsum[rs_off + row];
            float s1 = 1.0f / g_rowsum[rs_off + row + 8];
#pragma unroll
            for (int nj = 0; nj < 8; ++nj) {
                int col = j0 + n0 + nj * 8 + tc;
                *reinterpret_cast<float2*>(C + (size_t)row * ldc + col) =
                    make_float2(acc[mi][nj][0] * s0, acc[mi][nj][1] * s0);
                *reinterpret_cast<float2*>(C + (size_t)(row + 8) * ldc + col) =
                    make_float2(acc[mi][nj][2] * s1, acc[mi][nj][3] * s1);
            }
        }
    }
}

// ---------------- GEMM stage kernels ------------------------------------------
__global__ void __launch_bounds__(256, 2)
proj_qkv_tc()    // merged Q/K/V projection: z selects weight + output + epilogue
{
    const int z  = blockIdx.z;
    const int i0 = blockIdx.y * 128, j0 = blockIdx.x * 128;
    const __half* Bh = g_WThi + (size_t)z * DIM * DIM;
    if (z == 2) {
        gemm_pipe<5>(g_Xhi, DIM, Bh, DIM, nullptr, nullptr, DIM, i0, j0, DIM, 0);
    } else {
        __half* Ch = (z == 0) ? g_Qhi : g_Khi;
        gemm_pipe<4>(g_Xhi, DIM, Bh, DIM, nullptr, Ch, DIM, i0, j0, DIM, 0);
    }
}

__global__ void __launch_bounds__(256, 2)
scores_tc()
{
    // triangular tile decode: t -> (i >= j)
    const int t = blockIdx.x;
    int i = (int)((sqrtf(8.0f * t + 1.0f) - 1.0f) * 0.5f);
    while ((i + 1) * (i + 2) / 2 <= t) ++i;
    while (i * (i + 1) / 2 > t) --i;
    const int j = t - i * (i + 1) / 2;
    const int i0 = i * 128, j0 = j * 128;

    const size_t off = (size_t)blockIdx.z * SEQ * DIM;
    __half* Ch = g_Phi + (size_t)blockIdx.z * SEQ * SEQ;
    gemm_pipe<2>(g_Qhi + off, DIM, g_Khi + off, DIM,
                 nullptr, Ch, SEQ, i0, j0, DIM, blockIdx.z * SEQ);
}

__global__ void __launch_bounds__(256, 2)
pv_tc(float* __restrict__ out)
{
    const int i0 = blockIdx.y * 128, j0 = blockIdx.x * 128;
    const size_t poff = (size_t)blockIdx.z * SEQ * SEQ;
    const size_t voff = (size_t)blockIdx.z * DIM * SEQ;
    float* C = out + (size_t)blockIdx.z * SEQ * DIM;
    gemm_pipe<3>(g_Phi + poff, SEQ, g_VThi + voff, SEQ,
                 C, nullptr, DIM, i0, j0, i0 + 128, blockIdx.z * SEQ);
}

// ---------------- rowsum reduce (deterministic) ---------------------------------
__global__ void __launch_bounds__(256)
reduce_rowsum()
{
    const int i = blockIdx.x * 256 + threadIdx.x;
    const int q = i & (SEQ - 1);
    const int nt = (q >> 7) + 1;
    const float* p = g_partial + (size_t)i * 32;
    float s = 0.f;
    for (int t = 0; t < nt; ++t) s += p[t];
    g_rowsum[i] = s;
}

// ---------------- conversion / transpose kernels -------------------------------
__global__ void conv_x(const float* __restrict__ X)
{
    size_t i = (size_t)blockIdx.x * blockDim.x + threadIdx.x;
    const size_t n4 = (size_t)NTOK * DIM / 4;
    for (; i < n4; i += (size_t)gridDim.x * blockDim.x) {
        float4 v = reinterpret_cast<const float4*>(X)[i];
        reinterpret_cast<uint2*>(g_Xhi)[i] =
            make_uint2(pack2h(v.x, v.y), pack2h(v.z, v.w));
    }
}

__global__ void transpose_w(const float* __restrict__ Wq,
                            const float* __restrict__ Wk,
                            const float* __restrict__ Wv)
{
    const float* src = (blockIdx.z == 0) ? Wq : (blockIdx.z == 1) ? Wk : Wv;
    __half* dh = g_WThi + (size_t)blockIdx.z * DIM * DIM;
    __shared__ float t[32][33];
    const int bx = blockIdx.x * 32, by = blockIdx.y * 32;
    const int tx = threadIdx.x, ty = threadIdx.y;
#pragma unroll
    for (int j = 0; j < 32; j += 8)
        t[ty + j][tx] = src[(size_t)(by + ty + j) * DIM + bx + tx];
    __syncthreads();
#pragma unroll
    for (int j = 0; j < 32; j += 8)
        dh[(size_t)(bx + ty + j) * DIM + by + tx] = h_hi(t[tx][ty + j]);
}

// ---------------- launch ---------------------------------------------------------
extern "C" void kernel_launch(void* const* d_in, const int* in_sizes, int n_in,
                              void* d_out, int out_size)
{
    const float* x  = (const float*)d_in[0];
    const float* Wq = (const float*)d_in[1];
    const float* Wk = (const float*)d_in[2];
    const float* Wv = (const float*)d_in[3];
    float* out = (float*)d_out;

    cudaFuncSetAttribute(proj_qkv_tc, cudaFuncAttributeMaxDynamicSharedMemorySize, SMEM_BYTES);
    cudaFuncSetAttribute(scores_tc,   cudaFuncAttributeMaxDynamicSharedMemorySize, SMEM_BYTES);
    cudaFuncSetAttribute(pv_tc,       cudaFuncAttributeMaxDynamicSharedMemorySize, SMEM_BYTES);

    dim3 t32(32, 8);
    conv_x<<<512, 256>>>(x);
    transpose_w<<<dim3(DIM / 32, DIM / 32, 3), t32>>>(Wq, Wk, Wv);
    proj_qkv_tc<<<dim3(DIM / 128, NTOK / 128, 3), 256, SMEM_BYTES>>>();
    scores_tc<<<dim3(528, 1, BATCH), 256, SMEM_BYTES>>>();
    reduce_rowsum<<<NTOK / 256, 256>>>();
    pv_tc<<<dim3(DIM / 128, SEQ / 128, BATCH), 256, SMEM_BYTES>>>(out);
}

// round 17
// speedup vs baseline: 1.4249x; 1.0145x over previous
#include <cuda_runtime.h>
#include <cuda_fp16.h>
#include <cstdint>

#define BATCH 4
#define SEQ   4096
#define DIM   768
#define NTOK  (BATCH*SEQ)

// ---------------- scratch (__device__ globals: allocation-free rule) --------
__device__ __half g_Xhi [(size_t)NTOK * DIM];             // fp16 X
__device__ __half g_WThi[3ull * DIM * DIM];               // W^T fp16
__device__ __half g_Qhi [(size_t)NTOK * DIM];
__device__ __half g_Khi [(size_t)NTOK * DIM];
__device__ __half g_VThi[(size_t)BATCH * DIM * SEQ];      // V^T (written by proj epi)
__device__ __half g_Phi [(size_t)BATCH * SEQ * SEQ];      // exp(scores)/64, fp16
__device__ float g_partial[(size_t)NTOK * 32];            // per-(row,tile) sums

// ---------------- PTX helpers (arch-agnostic, sm_80-class) ------------------
__device__ __forceinline__ uint32_t smem_u32(const void* p) {
    uint32_t a;
    asm("{ .reg .u64 t; cvta.to.shared.u64 t, %1; cvt.u32.u64 %0, t; }"
        : "=r"(a) : "l"(p));
    return a;
}
__device__ __forceinline__ void cp16(uint32_t dst, const void* src) {
    asm volatile("cp.async.cg.shared.global [%0], [%1], 16;"
                 :: "r"(dst), "l"(src) : "memory");
}
#define CP_COMMIT() asm volatile("cp.async.commit_group;" ::: "memory")
#define CP_WAIT(N)  asm volatile("cp.async.wait_group %0;" :: "n"(N) : "memory")

__device__ __forceinline__ void ldsm_x4(uint32_t* r, uint32_t addr) {
    asm volatile("ldmatrix.sync.aligned.m8n8.x4.shared.b16 {%0,%1,%2,%3}, [%4];"
                 : "=r"(r[0]), "=r"(r[1]), "=r"(r[2]), "=r"(r[3]) : "r"(addr));
}
__device__ __forceinline__ void mma16816(float* d, const uint32_t* a, const uint32_t* b) {
    asm volatile(
        "mma.sync.aligned.m16n8k16.row.col.f32.f16.f16.f32 "
        "{%0,%1,%2,%3}, {%4,%5,%6,%7}, {%8,%9}, {%0,%1,%2,%3};"
        : "+f"(d[0]), "+f"(d[1]), "+f"(d[2]), "+f"(d[3])
        : "r"(a[0]), "r"(a[1]), "r"(a[2]), "r"(a[3]), "r"(b[0]), "r"(b[1]));
}

__device__ __forceinline__ uint32_t pack2h(float a, float b) {
    __half2 hv = __floats2half2_rn(a, b);
    return *reinterpret_cast<uint32_t*>(&hv);
}
__device__ __forceinline__ __half h_hi(float v) { return __float2half_rn(v); }

// ---------------- pipelined GEMM core (R12 shape: proven optimum) -------------
// C[128,128] = Ahi[128,K] * Bhi[128,K]^T, fp16 MMA, fp32 accum.
// 256 threads, 4(m) x 2(n) warps, warp tile 32x64, k-step 64, 2 CTAs/SM,
// 3-stage x 2 buffers (110.6 KB/CTA). Epilogues staged via smem for
// fully-coalesced 128-bit global stores.
#define LDSE 72
#define BUFB (128 * LDSE * 2)        // 18432 B
#define SMEM_BYTES 110592

#define SM_SCALE 0.03608439182435161f   // 1/sqrt(768)
#define P_SCALE  0.015625f              // store exp/64

// MODE 4: fp16 Chi (proj Q/K), staged.
// MODE 5: V -> g_VThi transposed via smem (proj V).
// MODE 2: exp/64 + causal mask + row partial sums; staged fp16 out (scores).
// MODE 3: fp32 out scaled by 1/rowsum (rowsum summed from g_partial in-CTA), staged.
template <int MODE>
__device__ __forceinline__ void gemm_pipe(
    const __half* __restrict__ Ahi, int lda,
    const __half* __restrict__ Bhi, int ldb,
    float* __restrict__ C, __half* __restrict__ Chi,
    int ldc, int i0, int j0, int K, int rs_off)
{
    extern __shared__ __align__(16) uint16_t dsm[];
    const uint32_t sb = smem_u32(dsm);

    const int tid  = threadIdx.x;
    const int wid  = tid >> 5;
    const int lane = tid & 31;
    const int m0 = (wid & 3) * 32;
    const int n0 = (wid >> 2) * 64;

    const int a_row = lane & 15;
    const int a_col = (lane >> 4) * 8;
    const int b_row = ((lane >> 4) & 1) * 8 + (lane & 7);
    const int b_col = ((lane >> 3) & 1) * 8;

    const __half* gsrc[2] = {Ahi, Bhi};
    const int glda[2] = {lda, ldb};
    const int grow[2] = {i0, j0};

    const int nk = K >> 6;

    auto stage = [&](int s, int kt) {
#pragma unroll
        for (int b = 0; b < 2; ++b) {
            uint32_t base = sb + (uint32_t)((s * 2 + b) * BUFB);
            const __half* g = gsrc[b];
#pragma unroll
            for (int k = 0; k < 4; ++k) {
                int u = tid + k * 256;
                int r = u >> 3, c = (u & 7) * 8;
                cp16(base + (uint32_t)(r * LDSE + c) * 2,
                     g + (size_t)(grow[b] + r) * glda[b] + kt + c);
            }
        }
        CP_COMMIT();
    };

    float acc[2][8][4] = {};

    stage(0, 0);
    if (nk > 1) stage(1, 64);
    for (int it = 0; it < nk; ++it) {
        const int s = it % 3;
        if (it + 2 < nk)       { stage((it + 2) % 3, (it + 2) << 6); CP_WAIT(2); }
        else if (it + 2 == nk) { CP_WAIT(1); }
        else                   { CP_WAIT(0); }
        __syncthreads();

        const uint32_t bAhi = sb + (uint32_t)((s * 2 + 0) * BUFB);
        const uint32_t bBhi = sb + (uint32_t)((s * 2 + 1) * BUFB);

#pragma unroll
        for (int kk = 0; kk < 64; kk += 16) {
            uint32_t aH[2][4];
#pragma unroll
            for (int mi = 0; mi < 2; ++mi) {
                uint32_t off = (uint32_t)((m0 + mi * 16 + a_row) * LDSE + kk + a_col) * 2;
                ldsm_x4(aH[mi], bAhi + off);
            }
#pragma unroll
            for (int nj = 0; nj < 4; ++nj) {
                uint32_t off = (uint32_t)((n0 + nj * 16 + b_row) * LDSE + kk + b_col) * 2;
                uint32_t bh[4];
                ldsm_x4(bh, bBhi + off);
#pragma unroll
                for (int mi = 0; mi < 2; ++mi) {
                    mma16816(acc[mi][nj * 2],     aH[mi], bh);
                    mma16816(acc[mi][nj * 2 + 1], aH[mi], bh + 2);
                }
            }
        }
        __syncthreads();   // also guarantees smem ring is dead before epilogue reuse
    }

    // ---- epilogue (smem-staged, coalesced stores) ------------------------------
    const int tr = lane >> 2;
    const int tc = (lane & 3) * 2;

    if (MODE == 4) {
        uint16_t* stg = dsm;                           // [128][136] fp16
#pragma unroll
        for (int mi = 0; mi < 2; ++mi)
#pragma unroll
            for (int nj = 0; nj < 8; ++nj) {
                int r  = m0 + mi * 16 + tr;
                int lc = n0 + nj * 8 + tc;
                *reinterpret_cast<uint32_t*>(&stg[(r    ) * 136 + lc]) =
                    pack2h(acc[mi][nj][0], acc[mi][nj][1]);
                *reinterpret_cast<uint32_t*>(&stg[(r + 8) * 136 + lc]) =
                    pack2h(acc[mi][nj][2], acc[mi][nj][3]);
            }
        __syncthreads();
#pragma unroll
        for (int k = 0; k < 8; ++k) {                  // 2048 16B-chunks
            int u = tid + k * 256;
            int r = u >> 4, tk = (u & 15) * 8;
            uint4 v = *reinterpret_cast<uint4*>(&stg[r * 136 + tk]);
            *reinterpret_cast<uint4*>(Chi + (size_t)(i0 + r) * ldc + j0 + tk) = v;
        }
    } else if (MODE == 5) {
        // V tile [128 tok x 128 d] -> smem [d][tok] -> coalesced g_VThi writes
        uint16_t* vt = dsm;                            // [128][136] fp16
#pragma unroll
        for (int mi = 0; mi < 2; ++mi)
#pragma unroll
            for (int nj = 0; nj < 8; ++nj) {
                int r = m0 + mi * 16 + tr;
                int c = n0 + nj * 8 + tc;
                vt[(c    ) * 136 + r    ] = __half_as_ushort(h_hi(acc[mi][nj][0]));
                vt[(c + 1) * 136 + r    ] = __half_as_ushort(h_hi(acc[mi][nj][1]));
                vt[(c    ) * 136 + r + 8] = __half_as_ushort(h_hi(acc[mi][nj][2]));
                vt[(c + 1) * 136 + r + 8] = __half_as_ushort(h_hi(acc[mi][nj][3]));
            }
        __syncthreads();
        const int b = i0 >> 12;
        const int seqr = i0 & (SEQ - 1);
#pragma unroll
        for (int k = 0; k < 8; ++k) {
            int u = tid + k * 256;
            int d = u >> 4, tk = (u & 15) * 8;
            uint4 v = *reinterpret_cast<uint4*>(&vt[d * 136 + tk]);
            *reinterpret_cast<uint4*>(
                g_VThi + ((size_t)b * DIM + j0 + d) * SEQ + seqr + tk) = v;
        }
    } else if (MODE == 2) {
        uint16_t* stg = dsm;                           // [128][136] fp16 (34816 B)
        float* red = reinterpret_cast<float*>(dsm + 128 * 136);  // 128 x 2 floats
        const int nwid = wid >> 2;
#pragma unroll
        for (int mi = 0; mi < 2; ++mi) {
#pragma unroll
            for (int rp = 0; rp < 2; ++rp) {
                const int lrow = m0 + mi * 16 + tr + rp * 8;
                const int row  = i0 + lrow;
                float part = 0.f;
#pragma unroll
                for (int nj = 0; nj < 8; ++nj) {
                    int lc  = n0 + nj * 8 + tc;
                    int col = j0 + lc;
                    float e0 = (col     <= row)
                        ? __expf(acc[mi][nj][rp * 2]     * SM_SCALE) * P_SCALE : 0.f;
                    float e1 = (col + 1 <= row)
                        ? __expf(acc[mi][nj][rp * 2 + 1] * SM_SCALE) * P_SCALE : 0.f;
                    *reinterpret_cast<uint32_t*>(&stg[lrow * 136 + lc]) = pack2h(e0, e1);
                    part += e0 + e1;
                }
                part += __shfl_xor_sync(0xffffffffu, part, 1);
                part += __shfl_xor_sync(0xffffffffu, part, 2);
                if ((lane & 3) == 0) red[lrow * 2 + nwid] = part;
            }
        }
        __syncthreads();
        if (tid < 128) {
            float s = red[tid * 2] + red[tid * 2 + 1];
            g_partial[(size_t)(rs_off + i0 + tid) * 32 + (j0 >> 7)] = s;
        }
#pragma unroll
        for (int k = 0; k < 8; ++k) {
            int u = tid + k * 256;
            int r = u >> 4, tk = (u & 15) * 8;
            uint4 v = *reinterpret_cast<uint4*>(&stg[r * 136 + tk]);
            *reinterpret_cast<uint4*>(Chi + (size_t)(i0 + r) * ldc + j0 + tk) = v;
        }
    } else {  // MODE 3: pv — in-CTA rowsum from g_partial, staged fp32 output
        float* stg  = reinterpret_cast<float*>(dsm);   // [128][132] fp32 (67584 B)
        float* rsum = stg + 128 * 132;                 // 128 floats
        const int nt = (((i0) & (SEQ - 1)) >> 7) + 1;  // valid tiles (tile-constant)
        if (tid < 128) {
            const float* p = g_partial + (size_t)(rs_off + i0 + tid) * 32;
            float s = 0.f;
            for (int t = 0; t < nt; ++t) s += p[t];
            rsum[tid] = 1.0f / s;
        }
        __syncthreads();
#pragma unroll
        for (int mi = 0; mi < 2; ++mi) {
            int lr = m0 + mi * 16 + tr;
            float s0 = rsum[lr];
            float s1 = rsum[lr + 8];
#pragma unroll
            for (int nj = 0; nj < 8; ++nj) {
                int lc = n0 + nj * 8 + tc;
                *reinterpret_cast<float2*>(&stg[(lr    ) * 132 + lc]) =
                    make_float2(acc[mi][nj][0] * s0, acc[mi][nj][1] * s0);
                *reinterpret_cast<float2*>(&stg[(lr + 8) * 132 + lc]) =
                    make_float2(acc[mi][nj][2] * s1, acc[mi][nj][3] * s1);
            }
        }
        __syncthreads();
#pragma unroll
        for (int k = 0; k < 16; ++k) {                 // 4096 16B-chunks
            int u = tid + k * 256;
            int r = u >> 5, c4 = (u & 31) * 4;
            float4 v = *reinterpret_cast<float4*>(&stg[r * 132 + c4]);
            *reinterpret_cast<float4*>(C + (size_t)(i0 + r) * ldc + j0 + c4) = v;
        }
    }
}

// ---------------- GEMM stage kernels ------------------------------------------
__global__ void __launch_bounds__(256, 2)
proj_qkv_tc()    // merged Q/K/V projection: z selects weight + output + epilogue
{
    const int z  = blockIdx.z;
    const int i0 = blockIdx.y * 128, j0 = blockIdx.x * 128;
    const __half* Bh = g_WThi + (size_t)z * DIM * DIM;
    if (z == 2) {
        gemm_pipe<5>(g_Xhi, DIM, Bh, DIM, nullptr, nullptr, DIM, i0, j0, DIM, 0);
    } else {
        __half* Ch = (z == 0) ? g_Qhi : g_Khi;
        gemm_pipe<4>(g_Xhi, DIM, Bh, DIM, nullptr, Ch, DIM, i0, j0, DIM, 0);
    }
}

__global__ void __launch_bounds__(256, 2)
scores_tc()
{
    // triangular tile decode: t -> (i >= j)
    const int t = blockIdx.x;
    int i = (int)((sqrtf(8.0f * t + 1.0f) - 1.0f) * 0.5f);
    while ((i + 1) * (i + 2) / 2 <= t) ++i;
    while (i * (i + 1) / 2 > t) --i;
    const int j = t - i * (i + 1) / 2;
    const int i0 = i * 128, j0 = j * 128;

    const size_t off = (size_t)blockIdx.z * SEQ * DIM;
    __half* Ch = g_Phi + (size_t)blockIdx.z * SEQ * SEQ;
    gemm_pipe<2>(g_Qhi + off, DIM, g_Khi + off, DIM,
                 nullptr, Ch, SEQ, i0, j0, DIM, blockIdx.z * SEQ);
}

__global__ void __launch_bounds__(256, 2)
pv_tc(float* __restrict__ out)
{
    const int i0 = blockIdx.y * 128, j0 = blockIdx.x * 128;
    const size_t poff = (size_t)blockIdx.z * SEQ * SEQ;
    const size_t voff = (size_t)blockIdx.z * DIM * SEQ;
    float* C = out + (size_t)blockIdx.z * SEQ * DIM;
    gemm_pipe<3>(g_Phi + poff, SEQ, g_VThi + voff, SEQ,
                 C, nullptr, DIM, i0, j0, i0 + 128, blockIdx.z * SEQ);
}

// ---------------- conversion / transpose kernels -------------------------------
__global__ void conv_x(const float* __restrict__ X)
{
    size_t i = (size_t)blockIdx.x * blockDim.x + threadIdx.x;
    const size_t n4 = (size_t)NTOK * DIM / 4;
    for (; i < n4; i += (size_t)gridDim.x * blockDim.x) {
        float4 v = reinterpret_cast<const float4*>(X)[i];
        reinterpret_cast<uint2*>(g_Xhi)[i] =
            make_uint2(pack2h(v.x, v.y), pack2h(v.z, v.w));
    }
}

__global__ void transpose_w(const float* __restrict__ Wq,
                            const float* __restrict__ Wk,
                            const float* __restrict__ Wv)
{
    const float* src = (blockIdx.z == 0) ? Wq : (blockIdx.z == 1) ? Wk : Wv;
    __half* dh = g_WThi + (size_t)blockIdx.z * DIM * DIM;
    __shared__ float t[32][33];
    const int bx = blockIdx.x * 32, by = blockIdx.y * 32;
    const int tx = threadIdx.x, ty = threadIdx.y;
#pragma unroll
    for (int j = 0; j < 32; j += 8)
        t[ty + j][tx] = src[(size_t)(by + ty + j) * DIM + bx + tx];
    __syncthreads();
#pragma unroll
    for (int j = 0; j < 32; j += 8)
        dh[(size_t)(bx + ty + j) * DIM + by + tx] = h_hi(t[tx][ty + j]);
}

// ---------------- launch ---------------------------------------------------------
extern "C" void kernel_launch(void* const* d_in, const int* in_sizes, int n_in,
                              void* d_out, int out_size)
{
    const float* x  = (const float*)d_in[0];
    const float* Wq = (const float*)d_in[1];
    const float* Wk = (const float*)d_in[2];
    const float* Wv = (const float*)d_in[3];
    float* out = (float*)d_out;

    cudaFuncSetAttribute(proj_qkv_tc, cudaFuncAttributeMaxDynamicSharedMemorySize, SMEM_BYTES);
    cudaFuncSetAttribute(scores_tc,   cudaFuncAttributeMaxDynamicSharedMemorySize, SMEM_BYTES);
    cudaFuncSetAttribute(pv_tc,       cudaFuncAttributeMaxDynamicSharedMemorySize, SMEM_BYTES);

    dim3 t32(32, 8);
    conv_x<<<512, 256>>>(x);
    transpose_w<<<dim3(DIM / 32, DIM / 32, 3), t32>>>(Wq, Wk, Wv);
    proj_qkv_tc<<<dim3(DIM / 128, NTOK / 128, 3), 256, SMEM_BYTES>>>();
    scores_tc<<<dim3(528, 1, BATCH), 256, SMEM_BYTES>>>();
    pv_tc<<<dim3(DIM / 128, SEQ / 128, BATCH), 256, SMEM_BYTES>>>(out);
}